// round 1
// baseline (speedup 1.0000x reference)
#include <cuda_runtime.h>
#include <math.h>

#define BB 16
#define NN 1024
#define FF 200
#define BN_ (BB*NN)          // 16384
#define C1 40
#define WO 35
#define KEFF 30
#define M4 560               // BB*WO
#define K4DIM 40960          // C1*NN
#define SPLIT 32
#define KSPL (K4DIM/SPLIT)   // 1280

// ---------------- scratch (static device globals; no dynamic alloc) ----------
__device__ float g_h[BN_*FF];          // 13.1 MB
__device__ float g_as[NN];
__device__ float g_ad[NN];
__device__ float g_xh[BN_*FF];         // 13.1 MB
__device__ float g_weff[C1*KEFF];
__device__ float g_woff[C1];
__device__ float g_y1[M4*K4DIM];       // 91.8 MB  [(b*35+w)][c*1024+n]
__device__ float g_y2p[SPLIT*M4*40];   // 2.9 MB
__device__ float g_y3[BB*1400];
__device__ float g_z[BB*1024];

// ---------------- K1: h = X(16384x200) @ gat_W(200x200) ----------------------
__global__ void k1_gemm(const float* __restrict__ x, const float* __restrict__ W){
  __shared__ float xs[32][200];
  int row0 = blockIdx.x*32;
  int tid = threadIdx.x;
  for (int idx=tid; idx<32*200; idx+=256)
    xs[idx/200][idx%200] = x[row0*200 + idx];
  __syncthreads();
  if (tid < 200){
    float acc[32];
    #pragma unroll
    for (int r=0;r<32;r++) acc[r]=0.f;
    for (int k0=0;k0<200;k0+=8){
      float w[8];
      #pragma unroll
      for (int q=0;q<8;q++) w[q]=W[(k0+q)*200+tid];
      #pragma unroll
      for (int r=0;r<32;r++){
        const float4* xp = reinterpret_cast<const float4*>(&xs[r][k0]);
        float4 xa = xp[0], xb = xp[1];
        acc[r] += xa.x*w[0]+xa.y*w[1]+xa.z*w[2]+xa.w*w[3]
                + xb.x*w[4]+xb.y*w[5]+xb.z*w[6]+xb.w*w[7];
      }
    }
    #pragma unroll
    for (int r=0;r<32;r++) g_h[(row0+r)*200+tid]=acc[r];
  }
}

// ---------------- K1b: attention scores a_s, a_d over first 1024 rows --------
__global__ void k1b_scores(const float* __restrict__ asw, const float* __restrict__ adw){
  int i = blockIdx.x;
  int lane = threadIdx.x;
  float s=0.f,d=0.f;
  for (int k=lane;k<200;k+=32){
    float hv=g_h[i*200+k];
    s+=hv*asw[k]; d+=hv*adw[k];
  }
  #pragma unroll
  for (int o=16;o>0;o>>=1){
    s+=__shfl_xor_sync(0xffffffffu,s,o);
    d+=__shfl_xor_sync(0xffffffffu,d,o);
  }
  if (lane==0){ g_as[i]=s; g_ad[i]=d; }
}

// ---------------- K2: dense GAT attention for graph 0 (1024x1024 softmax) ----
__global__ void k2_attn(const float* __restrict__ x, const float* __restrict__ gat_b){
  __shared__ float p[8][1024];
  __shared__ float red[8];
  __shared__ float rowsum[8];
  __shared__ float rowmax;
  int i0 = blockIdx.x*8;
  int tid = threadIdx.x;
  int lane = tid&31, wid = tid>>5;
  for (int ii=0; ii<8; ii++){
    float ad = g_ad[i0+ii];
    float mx = -1e30f;
    for (int j=tid;j<1024;j+=256){
      float v = g_as[j]+ad;
      float l = v>0.f? v : 0.2f*v;
      p[ii][j]=l;
      mx=fmaxf(mx,l);
    }
    #pragma unroll
    for (int o=16;o>0;o>>=1) mx=fmaxf(mx,__shfl_xor_sync(0xffffffffu,mx,o));
    if (lane==0) red[wid]=mx;
    __syncthreads();
    if (tid==0){
      float m=red[0];
      #pragma unroll
      for (int w2=1;w2<8;w2++) m=fmaxf(m,red[w2]);
      rowmax=m;
    }
    __syncthreads();
    float m = rowmax;
    float sum=0.f;
    for (int j=tid;j<1024;j+=256){
      float e=__expf(p[ii][j]-m);
      p[ii][j]=e;
      sum+=e;
    }
    #pragma unroll
    for (int o=16;o>0;o>>=1) sum+=__shfl_xor_sync(0xffffffffu,sum,o);
    __syncthreads();
    if (lane==0) red[wid]=sum;
    __syncthreads();
    if (tid==0){
      float s=0.f;
      #pragma unroll
      for (int w2=0;w2<8;w2++) s+=red[w2];
      rowsum[ii]=s;
    }
    __syncthreads();
  }
  if (tid<200){
    float acc[8];
    #pragma unroll
    for (int ii=0;ii<8;ii++) acc[ii]=0.f;
    for (int j=0;j<1024;j++){
      float hv = g_h[j*200+tid];
      #pragma unroll
      for (int ii=0;ii<8;ii++) acc[ii]+=p[ii][j]*hv;
    }
    float gb = gat_b[tid];
    #pragma unroll
    for (int ii=0;ii<8;ii++){
      int i=i0+ii;
      g_xh[i*200+tid] = x[i*200+tid] + acc[ii]/rowsum[ii] + gb;
    }
  }
}

// ---------------- K2b: residual for rows >= 1024 (self-loop only) ------------
__global__ void k2b_res(const float* __restrict__ x, const float* __restrict__ gat_b){
  int idx = blockIdx.x*256 + threadIdx.x + NN*FF;
  g_xh[idx] = x[idx] + g_h[idx] + gat_b[idx % FF];
}

// ---------------- K3a: fuse conv1 kernel + avgpool(5) + BN1 scale ------------
__global__ void k3a_weff(const float* __restrict__ cw, const float* __restrict__ cb,
                         const float* __restrict__ g, const float* __restrict__ bb,
                         const float* __restrict__ m, const float* __restrict__ v){
  int c = threadIdx.x;
  if (c < C1){
    float s = g[c]*rsqrtf(v[c]+1e-5f);
    g_woff[c] = (cb[c]-m[c])*s + bb[c];
    for (int j=0;j<KEFF;j++){
      float a=0.f;
      int t0 = (j-25>0)? j-25 : 0;
      int t1 = (j<4)? j : 4;
      for (int t=t0;t<=t1;t++) a += cw[c*26 + (j-t)];
      g_weff[c*KEFF+j] = a*0.2f*s;
    }
  }
}

// ---------------- K3: fused conv1+pool+BN1+ELU, writes y1 --------------------
__global__ void k3_conv(){
  __shared__ float xs[32][201];
  __shared__ float wf[C1*KEFF];
  __shared__ float off[C1];
  int n0 = blockIdx.x*32;
  int b  = blockIdx.y;
  int tid = threadIdx.x; // 224
  for (int idx=tid; idx<32*200; idx+=224)
    xs[idx/200][idx%200] = g_xh[(b*NN+n0)*200 + idx];
  for (int idx=tid; idx<C1*KEFF; idx+=224) wf[idx]=g_weff[idx];
  if (tid<C1) off[tid]=g_woff[tid];
  __syncthreads();
  int n  = tid & 31;
  int wg = tid >> 5;  // 0..6, w = wg*5 + i
  float xw[50];
  #pragma unroll
  for (int k=0;k<50;k++) xw[k]=xs[n][wg*25+k];
  for (int c=0;c<C1;c++){
    float wr[30];
    #pragma unroll
    for (int j=0;j<30;j++) wr[j]=wf[c*30+j];
    float oc = off[c];
    #pragma unroll
    for (int i=0;i<5;i++){
      float s = oc;
      #pragma unroll
      for (int j=0;j<30;j++) s += xw[5*i+j]*wr[j];
      float o = (s>0.f) ? s : expm1f(s);
      int w = wg*5+i;
      g_y1[((b*WO + w)*C1 + c)*NN + n0 + n] = o;
    }
  }
}

// ---------------- K4: conv2 as split-K GEMM (560 x 40, K=40960) --------------
__global__ void k4_gemm(const float* __restrict__ W){
  __shared__ float As[64][33];
  __shared__ float Bs[32][41];
  int m0 = blockIdx.x*64;
  int ks = blockIdx.y;
  int k0 = ks*KSPL;
  int tid = threadIdx.x; // 128
  int tm = tid & 15;
  int to = tid >> 4;     // 0..7
  float acc[4][5];
  #pragma unroll
  for (int i=0;i<4;i++)
    #pragma unroll
    for (int j=0;j<5;j++) acc[i][j]=0.f;
  for (int kc=0; kc<KSPL; kc+=32){
    int kk = k0+kc;
    #pragma unroll
    for (int l=0;l<16;l++){
      int idx = tid + l*128;
      int r = idx >> 5, k = idx & 31;
      int m = m0 + r;
      As[r][k] = (m < M4) ? g_y1[m*K4DIM + kk + k] : 0.f;
    }
    #pragma unroll
    for (int l=0;l<10;l++){
      int idx = tid + l*128;
      int o = idx >> 5, k = idx & 31;
      Bs[k][o] = W[o*K4DIM + kk + k];
    }
    __syncthreads();
    #pragma unroll
    for (int k=0;k<32;k++){
      float a0=As[tm*4+0][k], a1=As[tm*4+1][k], a2=As[tm*4+2][k], a3=As[tm*4+3][k];
      float b0=Bs[k][to*5+0], b1=Bs[k][to*5+1], b2=Bs[k][to*5+2],
            b3=Bs[k][to*5+3], b4=Bs[k][to*5+4];
      acc[0][0]+=a0*b0; acc[0][1]+=a0*b1; acc[0][2]+=a0*b2; acc[0][3]+=a0*b3; acc[0][4]+=a0*b4;
      acc[1][0]+=a1*b0; acc[1][1]+=a1*b1; acc[1][2]+=a1*b2; acc[1][3]+=a1*b3; acc[1][4]+=a1*b4;
      acc[2][0]+=a2*b0; acc[2][1]+=a2*b1; acc[2][2]+=a2*b2; acc[2][3]+=a2*b3; acc[2][4]+=a2*b4;
      acc[3][0]+=a3*b0; acc[3][1]+=a3*b1; acc[3][2]+=a3*b2; acc[3][3]+=a3*b3; acc[3][4]+=a3*b4;
    }
    __syncthreads();
  }
  #pragma unroll
  for (int i=0;i<4;i++){
    int m = m0 + tm*4 + i;
    if (m < M4){
      #pragma unroll
      for (int j=0;j<5;j++)
        g_y2p[(ks*M4 + m)*40 + to*5 + j] = acc[i][j];
    }
  }
}

// ---------------- K4b: split-K reduce + bias + BN2 + ELU + projc -------------
__global__ void k4b_epi(const float* __restrict__ cb2, const float* __restrict__ g2,
                        const float* __restrict__ bb2, const float* __restrict__ m2,
                        const float* __restrict__ v2, const float* __restrict__ pw,
                        const float* __restrict__ pb){
  __shared__ float vsh[40];
  int row = blockIdx.x;   // b*35+w
  int tid = threadIdx.x;  // 64
  if (tid<40){
    float acc = cb2[tid];
    for (int s=0;s<SPLIT;s++) acc += g_y2p[(s*M4+row)*40+tid];
    float sc = g2[tid]*rsqrtf(v2[tid]+1e-5f);
    float t = (acc - m2[tid])*sc + bb2[tid];
    vsh[tid] = (t>0.f)? t : expm1f(t);
  }
  __syncthreads();
  if (tid<40){
    float acc = pb[tid];
    #pragma unroll
    for (int o=0;o<40;o++) acc += vsh[o]*pw[tid*40+o];
    int b=row/WO, w=row%WO;
    g_y3[b*1400 + w*40 + tid] = acc;
  }
}

// ---------------- K5: z = y3(16x1400) @ W1(1400x1024) + b1 -------------------
__global__ void k5_fc1(const float* __restrict__ W1, const float* __restrict__ b1){
  __shared__ float ys[4][1400];
  int j = blockIdx.x*256 + threadIdx.x;
  int b0 = blockIdx.y*4;
  for (int i=threadIdx.x; i<4*1400; i+=256)
    ys[i/1400][i%1400] = g_y3[b0*1400 + i];
  __syncthreads();
  float a0,a1,a2,a3;
  a0=a1=a2=a3=b1[j];
  for (int i=0;i<1400;i++){
    float w = W1[i*1024+j];
    a0+=ys[0][i]*w; a1+=ys[1][i]*w; a2+=ys[2][i]*w; a3+=ys[3][i]*w;
  }
  g_z[(b0+0)*1024+j]=a0;
  g_z[(b0+1)*1024+j]=a1;
  g_z[(b0+2)*1024+j]=a2;
  g_z[(b0+3)*1024+j]=a3;
}

// ---------------- K6: z + gelu(z)@W2 + b2, then LayerNorm --------------------
__global__ void k6_fc2ln(const float* __restrict__ W2, const float* __restrict__ b2,
                         const float* __restrict__ lng, const float* __restrict__ lnb,
                         float* __restrict__ out){
  __shared__ float gs[1024];
  __shared__ float red[32];
  __shared__ float sMu, sVar;
  int b = blockIdx.x, j = threadIdx.x;
  int lane=j&31, wid=j>>5;
  float zv = g_z[b*1024+j];
  float ge = 0.5f*zv*(1.f+erff(zv*0.7071067811865476f));
  gs[j]=ge;
  __syncthreads();
  float acc=b2[j];
  for (int i=0;i<1024;i++) acc += gs[i]*W2[i*1024+j];
  float z2 = zv + acc;
  float s=z2;
  #pragma unroll
  for (int o=16;o>0;o>>=1) s+=__shfl_xor_sync(0xffffffffu,s,o);
  if (lane==0) red[wid]=s;
  __syncthreads();
  if (wid==0){
    float t=red[lane];
    #pragma unroll
    for (int o=16;o>0;o>>=1) t+=__shfl_xor_sync(0xffffffffu,t,o);
    if (lane==0) sMu = t*(1.f/1024.f);
  }
  __syncthreads();
  float mu=sMu;
  float d=z2-mu;
  s=d*d;
  #pragma unroll
  for (int o=16;o>0;o>>=1) s+=__shfl_xor_sync(0xffffffffu,s,o);
  __syncthreads();
  if (lane==0) red[wid]=s;
  __syncthreads();
  if (wid==0){
    float t=red[lane];
    #pragma unroll
    for (int o=16;o>0;o>>=1) t+=__shfl_xor_sync(0xffffffffu,t,o);
    if (lane==0) sVar = t*(1.f/1024.f);
  }
  __syncthreads();
  out[b*1024+j] = d*rsqrtf(sVar+1e-5f)*lng[j] + lnb[j];
}

// ---------------- launch ------------------------------------------------------
extern "C" void kernel_launch(void* const* d_in, const int* in_sizes, int n_in,
                              void* d_out, int out_size) {
  const float* x       = (const float*)d_in[0];
  const float* gat_W   = (const float*)d_in[1];
  const float* att_src = (const float*)d_in[2];
  const float* att_dst = (const float*)d_in[3];
  const float* gat_b   = (const float*)d_in[4];
  const float* conv1_w = (const float*)d_in[5];
  const float* conv1_b = (const float*)d_in[6];
  const float* bn1_g   = (const float*)d_in[7];
  const float* bn1_b   = (const float*)d_in[8];
  const float* bn1_m   = (const float*)d_in[9];
  const float* bn1_v   = (const float*)d_in[10];
  const float* conv2_w = (const float*)d_in[11];
  const float* conv2_b = (const float*)d_in[12];
  const float* bn2_g   = (const float*)d_in[13];
  const float* bn2_b   = (const float*)d_in[14];
  const float* bn2_m   = (const float*)d_in[15];
  const float* bn2_v   = (const float*)d_in[16];
  const float* projc_w = (const float*)d_in[17];
  const float* projc_b = (const float*)d_in[18];
  const float* W1      = (const float*)d_in[19];
  const float* b1      = (const float*)d_in[20];
  const float* W2      = (const float*)d_in[21];
  const float* b2      = (const float*)d_in[22];
  const float* ln_g    = (const float*)d_in[23];
  const float* ln_b    = (const float*)d_in[24];
  float* out = (float*)d_out;

  k1_gemm<<<BN_/32, 256>>>(x, gat_W);
  k1b_scores<<<NN, 32>>>(att_src, att_dst);
  k2_attn<<<NN/8, 256>>>(x, gat_b);
  k2b_res<<<(BN_-NN)*FF/256, 256>>>(x, gat_b);
  k3a_weff<<<1, 64>>>(conv1_w, conv1_b, bn1_g, bn1_b, bn1_m, bn1_v);
  k3_conv<<<dim3(NN/32, BB), 224>>>();
  k4_gemm<<<dim3(9, SPLIT), 128>>>(conv2_w);
  k4b_epi<<<M4, 64>>>(conv2_b, bn2_g, bn2_b, bn2_m, bn2_v, projc_w, projc_b);
  k5_fc1<<<dim3(4, 4), 256>>>(W1, b1);
  k6_fc2ln<<<BB, 1024>>>(W2, b2, ln_g, ln_b, out);
}

// round 2
// speedup vs baseline: 1.2512x; 1.2512x over previous
#include <cuda_runtime.h>
#include <math.h>

#define BB 16
#define NN 1024
#define FF 200
#define BN_ (BB*NN)          // 16384
#define C1 40
#define WO 35
#define KEFF 30
#define M4 560               // BB*WO
#define K4DIM 40960          // C1*NN
#define SPLIT 64
#define KSPL (K4DIM/SPLIT)   // 640

// ---------------- packed fp32x2 FMA (sm_103a) --------------------------------
__device__ __forceinline__ float2 ffma2(float2 a, float2 b, float2 c){
  unsigned long long ra = *reinterpret_cast<unsigned long long*>(&a);
  unsigned long long rb = *reinterpret_cast<unsigned long long*>(&b);
  unsigned long long rc = *reinterpret_cast<unsigned long long*>(&c);
  unsigned long long rd;
  asm("fma.rn.f32x2 %0, %1, %2, %3;" : "=l"(rd) : "l"(ra), "l"(rb), "l"(rc));
  return *reinterpret_cast<float2*>(&rd);
}

// ---------------- scratch ------------------------------------------------------
__device__ float g_h[BN_*FF];          // 13.1 MB
__device__ float g_as[NN];
__device__ float g_ad[NN];
__device__ float g_xh[BN_*FF];         // 13.1 MB
__device__ float g_weff[C1*KEFF];
__device__ float g_woff[C1];
__device__ float g_y1[M4*K4DIM];       // 91.8 MB  [(b*35+w)][c*1024+n]
__device__ float g_y2p[SPLIT*M4*40];   // 5.7 MB
__device__ float g_y3[BB*1400];
__device__ float g_zp[8*BB*1024];      // FC1 split-K partials
__device__ float g_z[BB*1024];
__device__ float g_z2p[8*BB*1024];     // FC2 split-K partials

// ---------------- K1: h = X(16384x200) @ gat_W(200x200), FFMA2 over row-pairs -
__global__ void k1_gemm(const float* __restrict__ x, const float* __restrict__ W){
  __shared__ float2 xt[200][17];   // xt[k][rp] = (x[2rp][k], x[2rp+1][k])
  int row0 = blockIdx.x*32;
  int tid = threadIdx.x;           // 256
  for (int idx=tid; idx<32*200; idx+=256){
    int row = idx/200, k = idx%200;
    float v = x[row0*200 + idx];
    ((float*)xt)[(k*17 + (row>>1))*2 + (row&1)] = v;
  }
  __syncthreads();
  if (tid < 200){
    int j = tid;
    float2 acc[16];
    #pragma unroll
    for (int r=0;r<16;r++) acc[r]=make_float2(0.f,0.f);
    #pragma unroll 4
    for (int k=0;k<200;k++){
      float wv = W[k*200+j];
      float2 w2 = make_float2(wv,wv);
      #pragma unroll
      for (int rp=0;rp<16;rp++)
        acc[rp] = ffma2(xt[k][rp], w2, acc[rp]);
    }
    #pragma unroll
    for (int rp=0;rp<16;rp++){
      g_h[(row0+2*rp  )*200+j] = acc[rp].x;
      g_h[(row0+2*rp+1)*200+j] = acc[rp].y;
    }
  }
}

// ---------------- K1b: attention scores ---------------------------------------
__global__ void k1b_scores(const float* __restrict__ asw, const float* __restrict__ adw){
  int i = blockIdx.x;
  int lane = threadIdx.x;
  float s=0.f,d=0.f;
  for (int k=lane;k<200;k+=32){
    float hv=g_h[i*200+k];
    s+=hv*asw[k]; d+=hv*adw[k];
  }
  #pragma unroll
  for (int o=16;o>0;o>>=1){
    s+=__shfl_xor_sync(0xffffffffu,s,o);
    d+=__shfl_xor_sync(0xffffffffu,d,o);
  }
  if (lane==0){ g_as[i]=s; g_ad[i]=d; }
}

// ---------------- K2: dense GAT attention for graph 0 -------------------------
__global__ void k2_attn(const float* __restrict__ x, const float* __restrict__ gat_b){
  __shared__ float p[8][1024];
  __shared__ float red[8];
  __shared__ float rowsum[8];
  __shared__ float rowmax;
  int i0 = blockIdx.x*8;
  int tid = threadIdx.x;
  int lane = tid&31, wid = tid>>5;
  for (int ii=0; ii<8; ii++){
    float ad = g_ad[i0+ii];
    float mx = -1e30f;
    for (int j=tid;j<1024;j+=256){
      float v = g_as[j]+ad;
      float l = v>0.f? v : 0.2f*v;
      p[ii][j]=l;
      mx=fmaxf(mx,l);
    }
    #pragma unroll
    for (int o=16;o>0;o>>=1) mx=fmaxf(mx,__shfl_xor_sync(0xffffffffu,mx,o));
    if (lane==0) red[wid]=mx;
    __syncthreads();
    if (tid==0){
      float m=red[0];
      #pragma unroll
      for (int w2=1;w2<8;w2++) m=fmaxf(m,red[w2]);
      rowmax=m;
    }
    __syncthreads();
    float m = rowmax;
    float sum=0.f;
    for (int j=tid;j<1024;j+=256){
      float e=__expf(p[ii][j]-m);
      p[ii][j]=e;
      sum+=e;
    }
    #pragma unroll
    for (int o=16;o>0;o>>=1) sum+=__shfl_xor_sync(0xffffffffu,sum,o);
    __syncthreads();
    if (lane==0) red[wid]=sum;
    __syncthreads();
    if (tid==0){
      float s=0.f;
      #pragma unroll
      for (int w2=0;w2<8;w2++) s+=red[w2];
      rowsum[ii]=s;
    }
    __syncthreads();
  }
  if (tid<200){
    float acc[8];
    #pragma unroll
    for (int ii=0;ii<8;ii++) acc[ii]=0.f;
    for (int j=0;j<1024;j++){
      float hv = g_h[j*200+tid];
      #pragma unroll
      for (int ii=0;ii<8;ii++) acc[ii]+=p[ii][j]*hv;
    }
    float gb = gat_b[tid];
    #pragma unroll
    for (int ii=0;ii<8;ii++){
      int i=i0+ii;
      g_xh[i*200+tid] = x[i*200+tid] + acc[ii]/rowsum[ii] + gb;
    }
  }
}

// ---------------- K2b: residual for rows >= 1024 (float4) ---------------------
__global__ void k2b_res(const float* __restrict__ x, const float* __restrict__ gat_b){
  int t = blockIdx.x*256 + threadIdx.x;
  int i4 = NN*FF/4 + t;    // float4 index
  const float4* x4 = (const float4*)x;
  const float4* h4 = (const float4*)g_h;
  float4* o4 = (float4*)g_xh;
  float4 xv = x4[i4], hv = h4[i4];
  int f0 = (i4*4) % FF;    // FF%4==0 so no wrap within a float4
  float4 r;
  r.x = xv.x + hv.x + gat_b[f0];
  r.y = xv.y + hv.y + gat_b[f0+1];
  r.z = xv.z + hv.z + gat_b[f0+2];
  r.w = xv.w + hv.w + gat_b[f0+3];
  o4[i4] = r;
}

// ---------------- K3a: fold conv1 + pool(5) + BN1 into effective weights ------
__global__ void k3a_weff(const float* __restrict__ cw, const float* __restrict__ cb,
                         const float* __restrict__ g, const float* __restrict__ bb,
                         const float* __restrict__ m, const float* __restrict__ v){
  int c = threadIdx.x;
  if (c < C1){
    float s = g[c]*rsqrtf(v[c]+1e-5f);
    g_woff[c] = (cb[c]-m[c])*s + bb[c];
    for (int j=0;j<KEFF;j++){
      float a=0.f;
      int t0 = (j-25>0)? j-25 : 0;
      int t1 = (j<4)? j : 4;
      for (int t=t0;t<=t1;t++) a += cw[c*26 + (j-t)];
      g_weff[c*KEFF+j] = a*0.2f*s;
    }
  }
}

// ---------------- K3: fused conv1+pool+BN1+ELU --------------------------------
__global__ void k3_conv(){
  __shared__ float xs[32][201];
  __shared__ float wf[C1*KEFF];
  __shared__ float off[C1];
  int n0 = blockIdx.x*32;
  int b  = blockIdx.y;
  int tid = threadIdx.x; // 224
  for (int idx=tid; idx<32*200; idx+=224)
    xs[idx/200][idx%200] = g_xh[(b*NN+n0)*200 + idx];
  for (int idx=tid; idx<C1*KEFF; idx+=224) wf[idx]=g_weff[idx];
  if (tid<C1) off[tid]=g_woff[tid];
  __syncthreads();
  int n  = tid & 31;
  int wg = tid >> 5;  // 0..6
  float xw[50];
  #pragma unroll
  for (int k=0;k<50;k++) xw[k]=xs[n][wg*25+k];
  for (int c=0;c<C1;c++){
    float wr[30];
    #pragma unroll
    for (int j=0;j<30;j++) wr[j]=wf[c*30+j];
    float oc = off[c];
    #pragma unroll
    for (int i=0;i<5;i++){
      float s = oc;
      #pragma unroll
      for (int j=0;j<30;j++) s += xw[5*i+j]*wr[j];
      float o = (s>0.f) ? s : expm1f(s);
      int w = wg*5+i;
      g_y1[((b*WO + w)*C1 + c)*NN + n0 + n] = o;
    }
  }
}

// ---------------- K4: conv2 GEMM (560x40, K=40960), split-K 64, FFMA2 ---------
__global__ void k4_gemm(const float* __restrict__ W){
  __shared__ float As[64][33];
  __shared__ float2 Bs2[32][21];   // Bs2[k][op] = (W[2op][k], W[2op+1][k])
  int m0 = blockIdx.x*64;
  int ks = blockIdx.y;
  int k0 = ks*KSPL;
  int tid = threadIdx.x;  // 160
  int tm = tid % 16;
  int to = tid / 16;      // 0..9, covers o = to*4 .. to*4+3
  float2 acc[4][2];
  #pragma unroll
  for (int i=0;i<4;i++){ acc[i][0]=make_float2(0.f,0.f); acc[i][1]=make_float2(0.f,0.f); }
  for (int kc=0; kc<KSPL; kc+=32){
    int kk = k0+kc;
    for (int idx=tid; idx<2048; idx+=160){
      int r = idx >> 5, k = idx & 31;
      int m = m0 + r;
      As[r][k] = (m < M4) ? g_y1[m*K4DIM + kk + k] : 0.f;
    }
    for (int idx=tid; idx<1280; idx+=160){
      int o = idx >> 5, k = idx & 31;
      ((float*)Bs2)[(k*21 + (o>>1))*2 + (o&1)] = W[o*K4DIM + kk + k];
    }
    __syncthreads();
    #pragma unroll
    for (int k=0;k<32;k++){
      float2 b0 = Bs2[k][to*2], b1 = Bs2[k][to*2+1];
      #pragma unroll
      for (int i=0;i<4;i++){
        float a = As[tm*4+i][k];
        float2 a2 = make_float2(a,a);
        acc[i][0] = ffma2(a2, b0, acc[i][0]);
        acc[i][1] = ffma2(a2, b1, acc[i][1]);
      }
    }
    __syncthreads();
  }
  #pragma unroll
  for (int i=0;i<4;i++){
    int m = m0 + tm*4 + i;
    if (m < M4){
      float* dst = &g_y2p[(ks*M4 + m)*40 + to*4];
      dst[0]=acc[i][0].x; dst[1]=acc[i][0].y; dst[2]=acc[i][1].x; dst[3]=acc[i][1].y;
    }
  }
}

// ---------------- K4b: split-K reduce + BN2 + ELU + projc ---------------------
__global__ void k4b_epi(const float* __restrict__ cb2, const float* __restrict__ g2,
                        const float* __restrict__ bb2, const float* __restrict__ m2,
                        const float* __restrict__ v2, const float* __restrict__ pw,
                        const float* __restrict__ pb){
  __shared__ float vsh[40];
  int row = blockIdx.x;   // b*35+w
  int tid = threadIdx.x;  // 64
  if (tid<40){
    float acc = cb2[tid];
    for (int s=0;s<SPLIT;s++) acc += g_y2p[(s*M4+row)*40+tid];
    float sc = g2[tid]*rsqrtf(v2[tid]+1e-5f);
    float t = (acc - m2[tid])*sc + bb2[tid];
    vsh[tid] = (t>0.f)? t : expm1f(t);
  }
  __syncthreads();
  if (tid<40){
    float acc = pb[tid];
    #pragma unroll
    for (int o=0;o<40;o++) acc += vsh[o]*pw[tid*40+o];
    int b=row/WO, w=row%WO;
    g_y3[b*1400 + w*40 + tid] = acc;
  }
}

// ---------------- K5: FC1 partial GEMM: (16x1400)@(1400x1024), K split 8 ------
__global__ void k5_fc1(const float* __restrict__ W1){
  __shared__ float ys[16][176];
  int jb = blockIdx.x, kc = blockIdx.y;
  int tid = threadIdx.x;  // 256
  for (int idx=tid; idx<16*175; idx+=256){
    int b = idx/175, ii = idx%175;
    ys[b][ii] = g_y3[b*1400 + kc*175 + ii];
  }
  __syncthreads();
  int j = jb*256 + tid;
  float acc[16];
  #pragma unroll
  for (int b=0;b<16;b++) acc[b]=0.f;
  for (int ii=0; ii<175; ii++){
    float w = W1[(kc*175+ii)*1024 + j];
    #pragma unroll
    for (int b=0;b<16;b++) acc[b] += ys[b][ii]*w;
  }
  #pragma unroll
  for (int b=0;b<16;b++)
    g_zp[(kc*16+b)*1024 + j] = acc[b];
}

// ---------------- K5b: reduce partials + b1 -> z -------------------------------
__global__ void k5b_red(const float* __restrict__ b1){
  int idx = blockIdx.x*256 + threadIdx.x;    // 0..16383
  int b = idx >> 10, j = idx & 1023;
  float acc = b1[j];
  #pragma unroll
  for (int kc=0;kc<8;kc++) acc += g_zp[(kc*16+b)*1024 + j];
  g_z[idx] = acc;
}

// ---------------- K6a: partial gelu(z)@W2, K split 8 ---------------------------
__global__ void k6a_fc2(const float* __restrict__ W2){
  __shared__ float gs[16][129];
  int jb = blockIdx.x, kc = blockIdx.y;
  int tid = threadIdx.x;  // 256
  for (int idx=tid; idx<16*128; idx+=256){
    int b = idx >> 7, ii = idx & 127;
    float zv = g_z[b*1024 + kc*128 + ii];
    gs[b][ii] = 0.5f*zv*(1.f+erff(zv*0.7071067811865476f));
  }
  __syncthreads();
  int j = jb*256 + tid;
  float acc[16];
  #pragma unroll
  for (int b=0;b<16;b++) acc[b]=0.f;
  for (int ii=0; ii<128; ii++){
    float w = W2[(kc*128+ii)*1024 + j];
    #pragma unroll
    for (int b=0;b<16;b++) acc[b] += gs[b][ii]*w;
  }
  #pragma unroll
  for (int b=0;b<16;b++)
    g_z2p[(kc*16+b)*1024 + j] = acc[b];
}

// ---------------- K6b: z2 = z + partials + b2, LayerNorm -----------------------
__global__ void k6b_ln(const float* __restrict__ b2, const float* __restrict__ lng,
                       const float* __restrict__ lnb, float* __restrict__ out){
  __shared__ float red[32];
  __shared__ float sMu, sVar;
  int b = blockIdx.x, j = threadIdx.x;
  int lane=j&31, wid=j>>5;
  float acc = g_z[b*1024+j] + b2[j];
  #pragma unroll
  for (int kc=0;kc<8;kc++) acc += g_z2p[(kc*16+b)*1024 + j];
  float z2 = acc;
  float s=z2;
  #pragma unroll
  for (int o=16;o>0;o>>=1) s+=__shfl_xor_sync(0xffffffffu,s,o);
  if (lane==0) red[wid]=s;
  __syncthreads();
  if (wid==0){
    float t=red[lane];
    #pragma unroll
    for (int o=16;o>0;o>>=1) t+=__shfl_xor_sync(0xffffffffu,t,o);
    if (lane==0) sMu = t*(1.f/1024.f);
  }
  __syncthreads();
  float mu=sMu;
  float d=z2-mu;
  s=d*d;
  #pragma unroll
  for (int o=16;o>0;o>>=1) s+=__shfl_xor_sync(0xffffffffu,s,o);
  if (lane==0) red[wid]=s;
  __syncthreads();
  if (wid==0){
    float t=red[lane];
    #pragma unroll
    for (int o=16;o>0;o>>=1) t+=__shfl_xor_sync(0xffffffffu,t,o);
    if (lane==0) sVar = t*(1.f/1024.f);
  }
  __syncthreads();
  out[b*1024+j] = d*rsqrtf(sVar+1e-5f)*lng[j] + lnb[j];
}

// ---------------- launch --------------------------------------------------------
extern "C" void kernel_launch(void* const* d_in, const int* in_sizes, int n_in,
                              void* d_out, int out_size) {
  const float* x       = (const float*)d_in[0];
  const float* gat_W   = (const float*)d_in[1];
  const float* att_src = (const float*)d_in[2];
  const float* att_dst = (const float*)d_in[3];
  const float* gat_b   = (const float*)d_in[4];
  const float* conv1_w = (const float*)d_in[5];
  const float* conv1_b = (const float*)d_in[6];
  const float* bn1_g   = (const float*)d_in[7];
  const float* bn1_b   = (const float*)d_in[8];
  const float* bn1_m   = (const float*)d_in[9];
  const float* bn1_v   = (const float*)d_in[10];
  const float* conv2_w = (const float*)d_in[11];
  const float* conv2_b = (const float*)d_in[12];
  const float* bn2_g   = (const float*)d_in[13];
  const float* bn2_b   = (const float*)d_in[14];
  const float* bn2_m   = (const float*)d_in[15];
  const float* bn2_v   = (const float*)d_in[16];
  const float* projc_w = (const float*)d_in[17];
  const float* projc_b = (const float*)d_in[18];
  const float* W1      = (const float*)d_in[19];
  const float* b1      = (const float*)d_in[20];
  const float* W2      = (const float*)d_in[21];
  const float* b2      = (const float*)d_in[22];
  const float* ln_g    = (const float*)d_in[23];
  const float* ln_b    = (const float*)d_in[24];
  float* out = (float*)d_out;

  k1_gemm<<<BN_/32, 256>>>(x, gat_W);
  k1b_scores<<<NN, 32>>>(att_src, att_dst);
  k2_attn<<<NN/8, 256>>>(x, gat_b);
  k2b_res<<<(BN_-NN)*FF/4/256, 256>>>(x, gat_b);
  k3a_weff<<<1, 64>>>(conv1_w, conv1_b, bn1_g, bn1_b, bn1_m, bn1_v);
  k3_conv<<<dim3(NN/32, BB), 224>>>();
  k4_gemm<<<dim3(9, SPLIT), 160>>>(conv2_w);
  k4b_epi<<<M4, 64>>>(conv2_b, bn2_g, bn2_b, bn2_m, bn2_v, projc_w, projc_b);
  k5_fc1<<<dim3(4, 8), 256>>>(W1);
  k5b_red<<<64, 256>>>(b1);
  k6a_fc2<<<dim3(4, 8), 256>>>(W2);
  k6b_ln<<<BB, 1024>>>(b2, ln_g, ln_b, out);
}

// round 3
// speedup vs baseline: 1.7335x; 1.3854x over previous
#include <cuda_runtime.h>
#include <math.h>

#define BB 16
#define NN 1024
#define FF 200
#define BN_ (BB*NN)          // 16384
#define C1 40
#define WO 35
#define KEFF 30
#define M4 560               // BB*WO
#define K4DIM 40960          // C1*NN
#define SPLIT 64
#define KSPL (K4DIM/SPLIT)   // 640
#define KC5 14               // FC1 k-split (1400/14 = 100)
#define KC6 8                // FC2 k-split (1024/8 = 128)

// ---------------- packed fp32x2 FMA (sm_103a) --------------------------------
__device__ __forceinline__ float2 ffma2(float2 a, float2 b, float2 c){
  unsigned long long ra = *reinterpret_cast<unsigned long long*>(&a);
  unsigned long long rb = *reinterpret_cast<unsigned long long*>(&b);
  unsigned long long rc = *reinterpret_cast<unsigned long long*>(&c);
  unsigned long long rd;
  asm("fma.rn.f32x2 %0, %1, %2, %3;" : "=l"(rd) : "l"(ra), "l"(rb), "l"(rc));
  return *reinterpret_cast<float2*>(&rd);
}

// ---------------- scratch ------------------------------------------------------
__device__ float g_h[BN_*FF];          // 13.1 MB
__device__ float g_as[NN];
__device__ float g_ad[NN];
__device__ float g_xh[BN_*FF];         // 13.1 MB
__device__ float g_weff[C1*KEFF];
__device__ float g_woff[C1];
__device__ float g_y1[M4*K4DIM];       // 91.8 MB  [(b*35+w)][c*1024+n]
__device__ float g_y2p[SPLIT*M4*40];   // 5.7 MB
__device__ float g_y3[BB*1400];
__device__ float g_zp[KC5*BB*1024];    // FC1 split-K partials
__device__ float g_z[BB*1024];
__device__ float g_z2p[KC6*BB*1024];   // FC2 split-K partials

// ---------------- K1: h = X(16384x200) @ gat_W(200x200), FFMA2 ----------------
__global__ void k1_gemm(const float* __restrict__ x, const float* __restrict__ W){
  __shared__ float2 xt[200][17];   // xt[k][rp] = (x[2rp][k], x[2rp+1][k])
  int row0 = blockIdx.x*32;
  int tid = threadIdx.x;           // 256
  for (int idx=tid; idx<32*200; idx+=256){
    int row = idx/200, k = idx%200;
    float v = x[row0*200 + idx];
    ((float*)xt)[(k*17 + (row>>1))*2 + (row&1)] = v;
  }
  __syncthreads();
  if (tid < 200){
    int j = tid;
    float2 acc[16];
    #pragma unroll
    for (int r=0;r<16;r++) acc[r]=make_float2(0.f,0.f);
    #pragma unroll 8
    for (int k=0;k<200;k++){
      float wv = W[k*200+j];
      float2 w2 = make_float2(wv,wv);
      #pragma unroll
      for (int rp=0;rp<16;rp++)
        acc[rp] = ffma2(xt[k][rp], w2, acc[rp]);
    }
    #pragma unroll
    for (int rp=0;rp<16;rp++){
      g_h[(row0+2*rp  )*200+j] = acc[rp].x;
      g_h[(row0+2*rp+1)*200+j] = acc[rp].y;
    }
  }
}

// ---------------- K1b: attention scores ---------------------------------------
__global__ void k1b_scores(const float* __restrict__ asw, const float* __restrict__ adw){
  int i = blockIdx.x;
  int lane = threadIdx.x;
  float s=0.f,d=0.f;
  for (int k=lane;k<200;k+=32){
    float hv=g_h[i*200+k];
    s+=hv*asw[k]; d+=hv*adw[k];
  }
  #pragma unroll
  for (int o=16;o>0;o>>=1){
    s+=__shfl_xor_sync(0xffffffffu,s,o);
    d+=__shfl_xor_sync(0xffffffffu,d,o);
  }
  if (lane==0){ g_as[i]=s; g_ad[i]=d; }
}

// ---------------- K2: dense GAT attention, tiled + prefetched ------------------
// Phase 1: warp-per-row softmax (no block barriers inside).
// Phase 2: weighted sum as GEMM with smem-staged g_h tiles (16 j per tile),
//          register prefetch of the next tile overlapping compute.
__global__ void k2_attn(const float* __restrict__ x, const float* __restrict__ gat_b){
  __shared__ float pT[1024][8];   // 32 KB, transposed: pT[j][i]
  __shared__ float hs[3200];      // 12.8 KB, one 16x200 tile of g_h
  __shared__ float rowsum[8];
  int i0 = blockIdx.x*8;
  int tid = threadIdx.x;          // 256
  int lane = tid&31, w = tid>>5;  // warp w handles row i0+w

  // --- softmax row w ---
  {
    float ad = g_ad[i0+w];
    float mx = -1e30f;
    for (int jj=lane; jj<1024; jj+=32){
      float v = g_as[jj]+ad;
      float l = v>0.f? v : 0.2f*v;
      pT[jj][w]=l;
      mx=fmaxf(mx,l);
    }
    #pragma unroll
    for (int o=16;o>0;o>>=1) mx=fmaxf(mx,__shfl_xor_sync(0xffffffffu,mx,o));
    float sum=0.f;
    for (int jj=lane; jj<1024; jj+=32){
      float e=__expf(pT[jj][w]-mx);
      pT[jj][w]=e;
      sum+=e;
    }
    #pragma unroll
    for (int o=16;o>0;o>>=1) sum+=__shfl_xor_sync(0xffffffffu,sum,o);
    if (lane==0) rowsum[w]=sum;
  }
  __syncthreads();

  // --- weighted sum: out[i][f] = sum_j p[i][j] * h[j][f] ---
  float acc[8];
  #pragma unroll
  for (int ii=0;ii<8;ii++) acc[ii]=0.f;
  float buf[13];
  // prefetch tile 0
  #pragma unroll
  for (int l=0;l<13;l++){
    int idx = tid + l*256;
    if (idx<3200) buf[l] = g_h[idx];
  }
  for (int t=0;t<64;t++){
    __syncthreads();               // hs free
    #pragma unroll
    for (int l=0;l<13;l++){
      int idx = tid + l*256;
      if (idx<3200) hs[idx]=buf[l];
    }
    if (t<63){
      #pragma unroll
      for (int l=0;l<13;l++){
        int idx = tid + l*256;
        if (idx<3200) buf[l] = g_h[(t+1)*3200 + idx];
      }
    }
    __syncthreads();               // hs ready
    if (tid<200){
      int j0 = t*16;
      #pragma unroll
      for (int jj=0;jj<16;jj++){
        float hv = hs[jj*200+tid];
        float4 pa = *reinterpret_cast<const float4*>(&pT[j0+jj][0]);
        float4 pb = *reinterpret_cast<const float4*>(&pT[j0+jj][4]);
        acc[0]+=pa.x*hv; acc[1]+=pa.y*hv; acc[2]+=pa.z*hv; acc[3]+=pa.w*hv;
        acc[4]+=pb.x*hv; acc[5]+=pb.y*hv; acc[6]+=pb.z*hv; acc[7]+=pb.w*hv;
      }
    }
  }
  if (tid<200){
    float gb = gat_b[tid];
    #pragma unroll
    for (int ii=0;ii<8;ii++){
      int i=i0+ii;
      g_xh[i*200+tid] = x[i*200+tid] + acc[ii]/rowsum[ii] + gb;
    }
  }
}

// ---------------- K2b: residual for rows >= 1024 (float4) ---------------------
__global__ void k2b_res(const float* __restrict__ x, const float* __restrict__ gat_b){
  int t = blockIdx.x*256 + threadIdx.x;
  int i4 = NN*FF/4 + t;
  const float4* x4 = (const float4*)x;
  const float4* h4 = (const float4*)g_h;
  float4* o4 = (float4*)g_xh;
  float4 xv = x4[i4], hv = h4[i4];
  int f0 = (i4*4) % FF;
  float4 r;
  r.x = xv.x + hv.x + gat_b[f0];
  r.y = xv.y + hv.y + gat_b[f0+1];
  r.z = xv.z + hv.z + gat_b[f0+2];
  r.w = xv.w + hv.w + gat_b[f0+3];
  o4[i4] = r;
}

// ---------------- K3a: fold conv1 + pool(5) + BN1 into effective weights ------
__global__ void k3a_weff(const float* __restrict__ cw, const float* __restrict__ cb,
                         const float* __restrict__ g, const float* __restrict__ bb,
                         const float* __restrict__ m, const float* __restrict__ v){
  int c = threadIdx.x;
  if (c < C1){
    float s = g[c]*rsqrtf(v[c]+1e-5f);
    g_woff[c] = (cb[c]-m[c])*s + bb[c];
    for (int j=0;j<KEFF;j++){
      float a=0.f;
      int t0 = (j-25>0)? j-25 : 0;
      int t1 = (j<4)? j : 4;
      for (int t=t0;t<=t1;t++) a += cw[c*26 + (j-t)];
      g_weff[c*KEFF+j] = a*0.2f*s;
    }
  }
}

// ---------------- K3: fused conv1+pool+BN1+ELU --------------------------------
__global__ void k3_conv(){
  __shared__ float xs[32][201];
  __shared__ float wf[C1*KEFF];
  __shared__ float off[C1];
  int n0 = blockIdx.x*32;
  int b  = blockIdx.y;
  int tid = threadIdx.x; // 224
  for (int idx=tid; idx<32*200; idx+=224)
    xs[idx/200][idx%200] = g_xh[(b*NN+n0)*200 + idx];
  for (int idx=tid; idx<C1*KEFF; idx+=224) wf[idx]=g_weff[idx];
  if (tid<C1) off[tid]=g_woff[tid];
  __syncthreads();
  int n  = tid & 31;
  int wg = tid >> 5;  // 0..6
  float xw[50];
  #pragma unroll
  for (int k=0;k<50;k++) xw[k]=xs[n][wg*25+k];
  for (int c=0;c<C1;c++){
    float wr[30];
    #pragma unroll
    for (int j=0;j<30;j++) wr[j]=wf[c*30+j];
    float oc = off[c];
    #pragma unroll
    for (int i=0;i<5;i++){
      float s = oc;
      #pragma unroll
      for (int j=0;j<30;j++) s += xw[5*i+j]*wr[j];
      float o = (s>0.f) ? s : expm1f(s);
      int w = wg*5+i;
      g_y1[((b*WO + w)*C1 + c)*NN + n0 + n] = o;
    }
  }
}

// ---------------- K4: conv2 GEMM (560x40, K=40960), split-K 64, prefetched ----
__global__ void k4_gemm(const float* __restrict__ W){
  __shared__ float As[64][33];
  __shared__ float2 Bs2[32][21];
  int m0 = blockIdx.x*64;
  int ks = blockIdx.y;
  int k0 = ks*KSPL;
  int tid = threadIdx.x;  // 160
  int tm = tid % 16;
  int to = tid / 16;      // 0..9
  float2 acc[4][2];
  #pragma unroll
  for (int i=0;i<4;i++){ acc[i][0]=make_float2(0.f,0.f); acc[i][1]=make_float2(0.f,0.f); }
  float ra[13], rb[8];
  // prefetch first tile
  #pragma unroll
  for (int l=0;l<13;l++){
    int idx = tid + l*160;
    if (idx<2048){
      int r = idx>>5, k = idx&31; int m = m0+r;
      ra[l] = (m<M4)? g_y1[m*K4DIM + k0 + k] : 0.f;
    }
  }
  #pragma unroll
  for (int l=0;l<8;l++){
    int idx = tid + l*160;
    int o = idx>>5, k = idx&31;
    rb[l] = W[o*K4DIM + k0 + k];
  }
  for (int kc=0; kc<KSPL; kc+=32){
    __syncthreads();
    #pragma unroll
    for (int l=0;l<13;l++){
      int idx = tid + l*160;
      if (idx<2048){ int r = idx>>5, k = idx&31; As[r][k]=ra[l]; }
    }
    #pragma unroll
    for (int l=0;l<8;l++){
      int idx = tid + l*160;
      int o = idx>>5, k = idx&31;
      ((float*)Bs2)[(k*21 + (o>>1))*2 + (o&1)] = rb[l];
    }
    if (kc+32<KSPL){
      int kk = k0+kc+32;
      #pragma unroll
      for (int l=0;l<13;l++){
        int idx = tid + l*160;
        if (idx<2048){
          int r = idx>>5, k = idx&31; int m = m0+r;
          ra[l] = (m<M4)? g_y1[m*K4DIM + kk + k] : 0.f;
        }
      }
      #pragma unroll
      for (int l=0;l<8;l++){
        int idx = tid + l*160;
        int o = idx>>5, k = idx&31;
        rb[l] = W[o*K4DIM + kk + k];
      }
    }
    __syncthreads();
    #pragma unroll
    for (int k=0;k<32;k++){
      float2 b0 = Bs2[k][to*2], b1 = Bs2[k][to*2+1];
      #pragma unroll
      for (int i=0;i<4;i++){
        float a = As[tm*4+i][k];
        float2 a2 = make_float2(a,a);
        acc[i][0] = ffma2(a2, b0, acc[i][0]);
        acc[i][1] = ffma2(a2, b1, acc[i][1]);
      }
    }
  }
  #pragma unroll
  for (int i=0;i<4;i++){
    int m = m0 + tm*4 + i;
    if (m < M4){
      float* dst = &g_y2p[(ks*M4 + m)*40 + to*4];
      dst[0]=acc[i][0].x; dst[1]=acc[i][0].y; dst[2]=acc[i][1].x; dst[3]=acc[i][1].y;
    }
  }
}

// ---------------- K4b: split-K reduce + BN2 + ELU + projc ---------------------
__global__ void k4b_epi(const float* __restrict__ cb2, const float* __restrict__ g2,
                        const float* __restrict__ bb2, const float* __restrict__ m2,
                        const float* __restrict__ v2, const float* __restrict__ pw,
                        const float* __restrict__ pb){
  __shared__ float vsh[40];
  int row = blockIdx.x;   // b*35+w
  int tid = threadIdx.x;  // 64
  if (tid<40){
    float acc = cb2[tid];
    #pragma unroll 8
    for (int s=0;s<SPLIT;s++) acc += g_y2p[(s*M4+row)*40+tid];
    float sc = g2[tid]*rsqrtf(v2[tid]+1e-5f);
    float t = (acc - m2[tid])*sc + bb2[tid];
    vsh[tid] = (t>0.f)? t : expm1f(t);
  }
  __syncthreads();
  if (tid<40){
    float acc = pb[tid];
    #pragma unroll
    for (int o=0;o<40;o++) acc += vsh[o]*pw[tid*40+o];
    int b=row/WO, w=row%WO;
    g_y3[b*1400 + w*40 + tid] = acc;
  }
}

// ---------------- K5: FC1 partial GEMM: (16x1400)@(1400x1024), K split 14 -----
__global__ void k5_fc1(const float* __restrict__ W1){
  __shared__ float ys[16][100];
  int jb = blockIdx.x, kc = blockIdx.y;
  int tid = threadIdx.x;  // 128
  for (int idx=tid; idx<1600; idx+=128){
    int b = idx/100, ii = idx%100;
    ys[b][ii] = g_y3[b*1400 + kc*100 + ii];
  }
  __syncthreads();
  int j = jb*128 + tid;
  float acc[16];
  #pragma unroll
  for (int b=0;b<16;b++) acc[b]=0.f;
  #pragma unroll 4
  for (int ii=0; ii<100; ii++){
    float w = W1[(kc*100+ii)*1024 + j];
    #pragma unroll
    for (int b=0;b<16;b++) acc[b] += ys[b][ii]*w;
  }
  #pragma unroll
  for (int b=0;b<16;b++)
    g_zp[(kc*16+b)*1024 + j] = acc[b];
}

// ---------------- K5b: reduce partials + b1 -> z -------------------------------
__global__ void k5b_red(const float* __restrict__ b1){
  int idx = blockIdx.x*256 + threadIdx.x;    // 0..16383
  int b = idx >> 10, j = idx & 1023;
  float acc = b1[j];
  #pragma unroll
  for (int kc=0;kc<KC5;kc++) acc += g_zp[(kc*16+b)*1024 + j];
  g_z[idx] = acc;
}

// ---------------- K6a: partial gelu(z)@W2, K split 8 ---------------------------
__global__ void k6a_fc2(const float* __restrict__ W2){
  __shared__ float gs[16][128];
  int jb = blockIdx.x, kc = blockIdx.y;
  int tid = threadIdx.x;  // 128
  for (int idx=tid; idx<2048; idx+=128){
    int b = idx >> 7, ii = idx & 127;
    float zv = g_z[b*1024 + kc*128 + ii];
    gs[b][ii] = 0.5f*zv*(1.f+erff(zv*0.7071067811865476f));
  }
  __syncthreads();
  int j = jb*128 + tid;
  float acc[16];
  #pragma unroll
  for (int b=0;b<16;b++) acc[b]=0.f;
  #pragma unroll 4
  for (int ii=0; ii<128; ii++){
    float w = W2[(kc*128+ii)*1024 + j];
    #pragma unroll
    for (int b=0;b<16;b++) acc[b] += gs[b][ii]*w;
  }
  #pragma unroll
  for (int b=0;b<16;b++)
    g_z2p[(kc*16+b)*1024 + j] = acc[b];
}

// ---------------- K6b: z2 = z + partials + b2, LayerNorm -----------------------
__global__ void k6b_ln(const float* __restrict__ b2, const float* __restrict__ lng,
                       const float* __restrict__ lnb, float* __restrict__ out){
  __shared__ float red[32];
  __shared__ float sMu, sVar;
  int b = blockIdx.x, j = threadIdx.x;
  int lane=j&31, wid=j>>5;
  float acc = g_z[b*1024+j] + b2[j];
  #pragma unroll
  for (int kc=0;kc<KC6;kc++) acc += g_z2p[(kc*16+b)*1024 + j];
  float z2 = acc;
  float s=z2;
  #pragma unroll
  for (int o=16;o>0;o>>=1) s+=__shfl_xor_sync(0xffffffffu,s,o);
  if (lane==0) red[wid]=s;
  __syncthreads();
  if (wid==0){
    float t=red[lane];
    #pragma unroll
    for (int o=16;o>0;o>>=1) t+=__shfl_xor_sync(0xffffffffu,t,o);
    if (lane==0) sMu = t*(1.f/1024.f);
  }
  __syncthreads();
  float mu=sMu;
  float d=z2-mu;
  s=d*d;
  #pragma unroll
  for (int o=16;o>0;o>>=1) s+=__shfl_xor_sync(0xffffffffu,s,o);
  if (lane==0) red[wid]=s;
  __syncthreads();
  if (wid==0){
    float t=red[lane];
    #pragma unroll
    for (int o=16;o>0;o>>=1) t+=__shfl_xor_sync(0xffffffffu,t,o);
    if (lane==0) sVar = t*(1.f/1024.f);
  }
  __syncthreads();
  out[b*1024+j] = d*rsqrtf(sVar+1e-5f)*lng[j] + lnb[j];
}

// ---------------- launch --------------------------------------------------------
extern "C" void kernel_launch(void* const* d_in, const int* in_sizes, int n_in,
                              void* d_out, int out_size) {
  const float* x       = (const float*)d_in[0];
  const float* gat_W   = (const float*)d_in[1];
  const float* att_src = (const float*)d_in[2];
  const float* att_dst = (const float*)d_in[3];
  const float* gat_b   = (const float*)d_in[4];
  const float* conv1_w = (const float*)d_in[5];
  const float* conv1_b = (const float*)d_in[6];
  const float* bn1_g   = (const float*)d_in[7];
  const float* bn1_b   = (const float*)d_in[8];
  const float* bn1_m   = (const float*)d_in[9];
  const float* bn1_v   = (const float*)d_in[10];
  const float* conv2_w = (const float*)d_in[11];
  const float* conv2_b = (const float*)d_in[12];
  const float* bn2_g   = (const float*)d_in[13];
  const float* bn2_b   = (const float*)d_in[14];
  const float* bn2_m   = (const float*)d_in[15];
  const float* bn2_v   = (const float*)d_in[16];
  const float* projc_w = (const float*)d_in[17];
  const float* projc_b = (const float*)d_in[18];
  const float* W1      = (const float*)d_in[19];
  const float* b1      = (const float*)d_in[20];
  const float* W2      = (const float*)d_in[21];
  const float* b2      = (const float*)d_in[22];
  const float* ln_g    = (const float*)d_in[23];
  const float* ln_b    = (const float*)d_in[24];
  float* out = (float*)d_out;

  k1_gemm<<<BN_/32, 256>>>(x, gat_W);
  k1b_scores<<<NN, 32>>>(att_src, att_dst);
  k2_attn<<<NN/8, 256>>>(x, gat_b);
  k2b_res<<<(BN_-NN)*FF/4/256, 256>>>(x, gat_b);
  k3a_weff<<<1, 64>>>(conv1_w, conv1_b, bn1_g, bn1_b, bn1_m, bn1_v);
  k3_conv<<<dim3(NN/32, BB), 224>>>();
  k4_gemm<<<dim3(9, SPLIT), 160>>>(conv2_w);
  k4b_epi<<<M4, 64>>>(conv2_b, bn2_g, bn2_b, bn2_m, bn2_v, projc_w, projc_b);
  k5_fc1<<<dim3(8, KC5), 128>>>(W1);
  k5b_red<<<64, 256>>>(b1);
  k6a_fc2<<<dim3(8, KC6), 128>>>(W2);
  k6b_ln<<<BB, 1024>>>(b2, ln_g, ln_b, out);
}